// round 4
// baseline (speedup 1.0000x reference)
#include <cuda_runtime.h>
#include <math.h>

#define EMB   64
#define NS    25
#define DEG   64
#define BATCH 4096
#define GRIDP 296              // persistent blocks (2/SM)

typedef unsigned long long ull;

// fma.rn.f32x2 — packed fp32 FMA (Blackwell). acc += a*b (two lanes)
#define FFMA2(acc, a, b) \
    asm("fma.rn.f32x2 %0, %1, %2, %3;" : "=l"(acc) : "l"(a), "l"(b), "l"(acc))

// A layout: [64 colgroups][16 k4][4 cols][4 k], group stride 260 floats
// (group stride 1040 B = 65 x 16B, odd -> conflict-free LDS.128 lane-striding)
#define A_GS 260
#define A_FLOATS (64 * A_GS)    // 16640

// ---------------- static device scratch (no allocation) --------------------
__device__ float g_At[A_FLOATS];              // folded layer-1 weights, blocked layout
__device__ float g_bias1[256];                // [b1x ; b1n]
__device__ float g_x0[128];                   // feats0 @ w1x.T (pre-relu)
__device__ float g_scr[(size_t)BATCH * 512];  // per batch: [h0x;h0n | h1mean(256)]

// ---------------------------------------------------------------------------
// prep_A: A1x/A1n = prep_W.T @ w1{x,n}.T, stored in blocked layout
// ---------------------------------------------------------------------------
__global__ void prep_A(const float* __restrict__ prep_W,
                       const float* __restrict__ w1x,
                       const float* __restrict__ w1n) {
    int idx = blockIdx.x * 128 + threadIdx.x;   // 0..8191
    int k = idx >> 7, h = idx & 127;
    float ax = 0.f, an = 0.f;
#pragma unroll
    for (int c = 0; c < 64; c++) {
        float p = prep_W[c * 64 + k];
        ax += p * w1x[h * 64 + c];
        an += p * w1n[h * 64 + c];
    }
    int cx = h, cn = 128 + h;
    g_At[(cx >> 2) * A_GS + (k >> 2) * 16 + (cx & 3) * 4 + (k & 3)] = ax;
    g_At[(cn >> 2) * A_GS + (k >> 2) * 16 + (cn & 3) * 4 + (k & 3)] = an;
}

// ---------------------------------------------------------------------------
// prep_B: x0 (h0 x-part, pre-relu) + folded biases   (1 block, 128 thr)
// ---------------------------------------------------------------------------
__global__ void prep_B(const float* __restrict__ emb,
                       const float* __restrict__ prep_W,
                       const float* __restrict__ prep_b,
                       const float* __restrict__ w1x,
                       const float* __restrict__ w1n,
                       int n_nodes) {
    __shared__ float f0[64];
    int t = threadIdx.x;
    if (t < 64) {
        const float* e = emb + (size_t)n_nodes * 64;
        float a = prep_b[t];
#pragma unroll
        for (int k = 0; k < 64; k++) a += e[k] * prep_W[t * 64 + k];
        f0[t] = a;
    }
    __syncthreads();
    float x0 = 0.f, bx = 0.f, bn = 0.f;
#pragma unroll
    for (int c = 0; c < 64; c++) {
        x0 += f0[c]     * w1x[t * 64 + c];
        bx += prep_b[c] * w1x[t * 64 + c];
        bn += prep_b[c] * w1n[t * 64 + c];
    }
    g_x0[t]          = x0;
    g_bias1[t]       = bx;
    g_bias1[128 + t] = bn;
}

// ---------------------------------------------------------------------------
// fused persistent kernel: 296 blocks, each loops over ~14 batch ids.
// Per iteration: gather NEXT batch's [e1|mean2] into the other feat buffer
// (memory phase), then GEMM current batch (fma phase), epilogue -> g_scr.
// smem floats: A 16640 | feats 2x3200 | H1 256 | mean 64 | bias 256 = 23616
// ---------------------------------------------------------------------------
#define SMO_F   A_FLOATS                       // 16640
#define SMO_H1  (SMO_F + 2 * NS * 128)         // 23040
#define SMO_MN  (SMO_H1 + 256)                 // 23296
#define SMO_B   (SMO_MN + 64)                  // 23360
#define SM_FLOATS (SMO_B + 256)                // 23616

__global__ void __launch_bounds__(256, 2)
fused_kernel(const float* __restrict__ emb,
             const int* __restrict__ ids,
             const int* __restrict__ adj,
             const int* __restrict__ perm1,
             const int* __restrict__ perm2) {
    extern __shared__ float sm[];
    float* sA    = sm;
    float* sH1   = sm + SMO_H1;
    float* sMean = sm + SMO_MN;
    float* sBias = sm + SMO_B;

    const int t = threadIdx.x;
    const int w = t >> 5, lane = t & 31;
    const float inv25 = 1.0f / 25.0f;

    // stage A (once per block) + bias + H1 init
    {
        const float4* src = (const float4*)g_At;
        float4* dst = (float4*)sA;
#pragma unroll
        for (int r = 0; r < 17; r++) {
            int idx = t + r * 256;
            if (idx < A_FLOATS / 4) dst[idx] = src[idx];
        }
        sBias[t] = g_bias1[t];
        sH1[t] = 0.f;
    }

    const int p2 = __ldg(&perm2[lane < NS ? lane : 0]);

    const int cg = t & 63;                 // column group -> cols c0..c0+3
    const int sg = t >> 6;                 // sample subset: s = sg + 4m
    const int c0 = cg * 4;
    const int kbase = (cg < 32) ? 0 : 64;  // e1-part vs mean2-part
    const float* Ab = sA + cg * A_GS;

    // ---- gather lambda-ish macro body (expanded inline twice) ----
#define GATHER(bi, bufsel)                                                     \
    do {                                                                       \
        float* sF_ = sm + SMO_F + (bufsel) * (NS * 128);                       \
        const int id0_ = __ldg(&ids[bi]);                                      \
        for (int j = w; j < NS; j += 8) {                                      \
            int id1 = __ldg(&adj[(size_t)id0_ * DEG + __ldg(&perm1[j])]);      \
            float2 e1 = *(const float2*)(emb + (size_t)id1 * 64 + 2 * lane);   \
            int nb = __ldg(&adj[(size_t)id1 * DEG + p2]);                      \
            float sx = 0.f, sy = 0.f;                                          \
            _Pragma("unroll")                                                  \
            for (int k = 0; k < NS; k++) {                                     \
                int idk = __shfl_sync(0xffffffffu, nb, k);                     \
                float2 v = *(const float2*)(emb + (size_t)idk * 64 + 2 * lane);\
                sx += v.x; sy += v.y;                                          \
            }                                                                  \
            *(float2*)(sF_ + j * 128 + 2 * lane) = e1;                         \
            *(float2*)(sF_ + j * 128 + 64 + 2 * lane)                          \
                = make_float2(sx * inv25, sy * inv25);                         \
        }                                                                      \
    } while (0)

    int i = blockIdx.x;
    if (i < BATCH) GATHER(i, 0);
    __syncthreads();

    int buf = 0;
    for (; i < BATCH; i += GRIDP) {
        const int nxt = i + GRIDP;
        if (nxt < BATCH) GATHER(nxt, buf ^ 1);

        // ---- GEMM on current buffer ----
        const float* fb = sm + SMO_F + buf * (NS * 128) + kbase;

        ull acc[7][4];
#pragma unroll
        for (int m = 0; m < 7; m++)
#pragma unroll
            for (int j = 0; j < 4; j++) acc[m][j] = 0ull;

#pragma unroll
        for (int k4 = 0; k4 < 16; k4++) {
            ulonglong2 a0 = *(const ulonglong2*)(Ab + k4 * 16);
            ulonglong2 a1 = *(const ulonglong2*)(Ab + k4 * 16 + 4);
            ulonglong2 a2 = *(const ulonglong2*)(Ab + k4 * 16 + 8);
            ulonglong2 a3 = *(const ulonglong2*)(Ab + k4 * 16 + 12);
#pragma unroll
            for (int m = 0; m < 7; m++) {
                int s = sg + 4 * m;
                if (s < NS) {
                    ulonglong2 f2 = *(const ulonglong2*)(fb + s * 128 + k4 * 4);
                    FFMA2(acc[m][0], f2.x, a0.x); FFMA2(acc[m][0], f2.y, a0.y);
                    FFMA2(acc[m][1], f2.x, a1.x); FFMA2(acc[m][1], f2.y, a1.y);
                    FFMA2(acc[m][2], f2.x, a2.x); FFMA2(acc[m][2], f2.y, a2.y);
                    FFMA2(acc[m][3], f2.x, a3.x); FFMA2(acc[m][3], f2.y, a3.y);
                }
            }
        }

        float hs[4] = {0.f, 0.f, 0.f, 0.f};
#pragma unroll
        for (int m = 0; m < 7; m++) {
            int s = sg + 4 * m;
            if (s < NS) {
#pragma unroll
                for (int j = 0; j < 4; j++) {
                    float lo = __uint_as_float((unsigned)acc[m][j]);
                    float hi = __uint_as_float((unsigned)(acc[m][j] >> 32));
                    hs[j] += fmaxf(lo + hi + sBias[c0 + j], 0.f);
                }
            }
        }
#pragma unroll
        for (int j = 0; j < 4; j++) atomicAdd(&sH1[c0 + j], hs[j]);

        // mean of e1 over 25 samples (for h0 neighbor branch)
        if (t < 64) {
            const float* sF_ = sm + SMO_F + buf * (NS * 128);
            float m = 0.f;
#pragma unroll
            for (int s = 0; s < NS; s++) m += sF_[s * 128 + t];
            sMean[t] = m * inv25;
        }
        __syncthreads();   // sH1 adds + sMean complete; next-buf gathers complete

        // ---- epilogue -> g_scr ----
        float* scr = g_scr + (size_t)i * 512;
        if (t < 128) {
            scr[t] = fmaxf(g_x0[t], 0.f);
        } else {
            int cgc = t >> 2, jc = t & 3;
            const float* Ac = sA + cgc * A_GS + jc * 4;
            float a = 0.f;
#pragma unroll
            for (int k4 = 0; k4 < 16; k4++) {
                float4 av = *(const float4*)(Ac + k4 * 16);
                float4 mv = *(const float4*)(sMean + k4 * 4);
                a += av.x * mv.x + av.y * mv.y + av.z * mv.z + av.w * mv.w;
            }
            scr[t] = fmaxf(a + sBias[t], 0.f);
        }
        scr[256 + t] = sH1[t] * inv25;
        sH1[t] = 0.f;                       // owner-thread reset
        __syncthreads();   // epilogue reads done before next iter's atomics

        buf ^= 1;
    }
#undef GATHER
}

// ---------------------------------------------------------------------------
// final_kernel: layer-2 matvecs (16 rows/block), thread = 2 cols x 8 rows,
// then L2-normalize + fc.
// ---------------------------------------------------------------------------
__global__ void __launch_bounds__(256)
final_kernel(const float* __restrict__ w2x,
             const float* __restrict__ w2n,
             const float* __restrict__ fcW,
             const float* __restrict__ fcb,
             float* __restrict__ out) {
    __shared__ float in_sh[16][512];
    __shared__ float sSq[16], sDot[16];
    int t  = threadIdx.x;
    int r0 = blockIdx.x * 16;

    {
        const float4* src = (const float4*)(g_scr + (size_t)r0 * 512);
        float4* dst = (float4*)&in_sh[0][0];
#pragma unroll
        for (int q = 0; q < 8; q++) dst[t + q * 256] = src[t + q * 256];
    }
    if (t < 16) { sSq[t] = 0.f; sDot[t] = 0.f; }
    __syncthreads();

    const int cp = t & 127;          // colpair -> cols 2cp, 2cp+1
    const int rh = t >> 7;           // row half -> rows rh*8 .. rh*8+7
    const int c0 = 2 * cp;
    const float* W0;
    int ioff;
    if (c0 < 128) { W0 = w2x + (size_t)c0 * 256;         ioff = 0;   }
    else          { W0 = w2n + (size_t)(c0 - 128) * 256; ioff = 256; }
    const float* W1 = W0 + 256;

    ull acc0[8], acc1[8];
#pragma unroll
    for (int r = 0; r < 8; r++) { acc0[r] = 0ull; acc1[r] = 0ull; }

    for (int c = 0; c < 256; c += 4) {
        ulonglong2 wv0 = *(const ulonglong2*)(W0 + c);
        ulonglong2 wv1 = *(const ulonglong2*)(W1 + c);
#pragma unroll
        for (int r = 0; r < 8; r++) {
            ulonglong2 x = *(const ulonglong2*)&in_sh[rh * 8 + r][ioff + c];
            FFMA2(acc0[r], x.x, wv0.x); FFMA2(acc0[r], x.y, wv0.y);
            FFMA2(acc1[r], x.x, wv1.x); FFMA2(acc1[r], x.y, wv1.y);
        }
    }

    float fw0 = fcW[c0], fw1 = fcW[c0 + 1];
#pragma unroll
    for (int r = 0; r < 8; r++) {
        int row = rh * 8 + r;
        float v0 = __uint_as_float((unsigned)acc0[r])
                 + __uint_as_float((unsigned)(acc0[r] >> 32));
        float v1 = __uint_as_float((unsigned)acc1[r])
                 + __uint_as_float((unsigned)(acc1[r] >> 32));
        float sq = v0 * v0 + v1 * v1;
        float dt = v0 * fw0 + v1 * fw1;
#pragma unroll
        for (int o = 16; o > 0; o >>= 1) {
            sq += __shfl_xor_sync(0xffffffffu, sq, o);
            dt += __shfl_xor_sync(0xffffffffu, dt, o);
        }
        if ((t & 31) == 0) { atomicAdd(&sSq[row], sq); atomicAdd(&sDot[row], dt); }
    }
    __syncthreads();
    if (t < 16) {
        float nrm = sqrtf(sSq[t]);
        out[r0 + t] = sDot[t] / fmaxf(nrm, 1e-12f) + fcb[0];
    }
}

// ---------------------------------------------------------------------------
extern "C" void kernel_launch(void* const* d_in, const int* in_sizes, int n_in,
                              void* d_out, int out_size) {
    const float* embedding = (const float*)d_in[0];
    const float* prep_W    = (const float*)d_in[1];
    const float* prep_b    = (const float*)d_in[2];
    const float* w1x       = (const float*)d_in[3];
    const float* w1n       = (const float*)d_in[4];
    const float* w2x       = (const float*)d_in[5];
    const float* w2n       = (const float*)d_in[6];
    const float* fcW       = (const float*)d_in[7];
    const float* fcb       = (const float*)d_in[8];
    const int*   ids       = (const int*)d_in[9];
    const int*   adj       = (const int*)d_in[10];
    const int*   perm1     = (const int*)d_in[11];
    const int*   perm2     = (const int*)d_in[12];
    const int n_nodes = in_sizes[0] / EMB - 1;

    prep_A<<<64, 128>>>(prep_W, w1x, w1n);
    prep_B<<<1, 128>>>(embedding, prep_W, prep_b, w1x, w1n, n_nodes);

    const int smem_f = SM_FLOATS * (int)sizeof(float);
    cudaFuncSetAttribute(fused_kernel, cudaFuncAttributeMaxDynamicSharedMemorySize, smem_f);
    fused_kernel<<<GRIDP, 256, smem_f>>>(embedding, ids, adj, perm1, perm2);

    final_kernel<<<BATCH / 16, 256>>>(w2x, w2n, fcW, fcb, (float*)d_out);
}